// round 8
// baseline (speedup 1.0000x reference)
#include <cuda_runtime.h>
#include <cuda_bf16.h>

#define NN 50000
#define NPAD 50048
#define EE 1600000
#define RR 7
#define DD 128
#define GG 64
#define NRSEG (NN * RR)          // 350000
#define SCAN_B 1024
#define NB1 ((NRSEG + SCAN_B - 1) / SCAN_B)

// ---------------- static device scratch ------------------------------------
__device__ float g_x[2][(size_t)NPAD * DD];      // ping-pong activations (fp32)
__device__ __nv_bfloat16 g_Wh[3 * 128 * 1024];   // [L][n][k] transposed, k-contig
__device__ __nv_bfloat16 g_Wl[3 * 128 * 1024];
__device__ float g_bias[3 * 128];
__device__ int   g_counts[NRSEG];
__device__ int   g_offs[NRSEG + 1];
__device__ int   g_cursor[NRSEG];
__device__ int   g_bsums[SCAN_B];
__device__ int2  g_edge[EE];                     // (src, __float_as_int(w)), seg-sorted

// ---------------- helpers ----------------------------------------------------
__device__ __forceinline__ unsigned s2u(const void* p) {
    unsigned a;
    asm("{ .reg .u64 t; cvta.to.shared.u64 t, %1; cvt.u32.u64 %0, t; }" : "=r"(a) : "l"(p));
    return a;
}
__device__ __forceinline__ void cp16(unsigned dst, const void* src) {
    asm volatile("cp.async.cg.shared.global [%0], [%1], 16;" :: "r"(dst), "l"(src) : "memory");
}
__device__ __forceinline__ void cp_commit() { asm volatile("cp.async.commit_group;" ::: "memory"); }
__device__ __forceinline__ void cp_wait1()  { asm volatile("cp.async.wait_group 1;" ::: "memory"); }
__device__ __forceinline__ void cp_wait0()  { asm volatile("cp.async.wait_group 0;" ::: "memory"); }

__device__ __forceinline__ void mma16816(float* c, const unsigned* a, const unsigned* b) {
    asm volatile(
        "mma.sync.aligned.m16n8k16.row.col.f32.bf16.bf16.f32 "
        "{%0,%1,%2,%3}, {%4,%5,%6,%7}, {%8,%9}, {%0,%1,%2,%3};"
        : "+f"(c[0]), "+f"(c[1]), "+f"(c[2]), "+f"(c[3])
        : "r"(a[0]), "r"(a[1]), "r"(a[2]), "r"(a[3]), "r"(b[0]), "r"(b[1]));
}

// ---------------- init: x0 = emb[unit_type] ---------------------------------
__global__ void k_init_x(const int* __restrict__ unit_type,
                         const float* __restrict__ emb) {
    int i = blockIdx.x * blockDim.x + threadIdx.x;
    if (i >= NN * DD) return;
    int n = i >> 7, d = i & 127;
    g_x[0][i] = emb[unit_type[n] * DD + d];
}

__global__ void k_zero_out(float* __restrict__ out) {
    int i = blockIdx.x * blockDim.x + threadIdx.x;
    if (i < GG * DD) out[i] = 0.0f;
}

// ---------------- weight transpose + bf16 split ------------------------------
__global__ void k_wconv(const float* __restrict__ Wrel,
                        const float* __restrict__ Wloop,
                        const float* __restrict__ brel,
                        const float* __restrict__ bloop) {
    int idx = blockIdx.x * blockDim.x + threadIdx.x;
    if (idx < 3 * 128 * 1024) {
        int L = idx >> 17;
        int r = idx & 131071;
        int n = r >> 10;
        int k = r & 1023;
        float w = (k < 896) ? Wrel[((size_t)L * 896 + k) * 128 + n]
                            : Wloop[((size_t)L * 128 + (k - 896)) * 128 + n];
        __nv_bfloat16 h = __float2bfloat16(w);
        g_Wh[idx] = h;
        g_Wl[idx] = __float2bfloat16(w - __bfloat162float(h));
    }
    if (idx < 3 * 128) g_bias[idx] = brel[idx] + bloop[idx];
}

// ---------------- CSR build --------------------------------------------------
__global__ void k_zero_counts() {
    int i = blockIdx.x * blockDim.x + threadIdx.x;
    if (i < NRSEG) g_counts[i] = 0;
}

__global__ void k_hist(const int* __restrict__ node_out,
                       const int* __restrict__ rel) {
    int i = blockIdx.x * blockDim.x + threadIdx.x;
    if (i < EE) atomicAdd(&g_counts[node_out[i] * RR + rel[i]], 1);
}

__device__ __forceinline__ void scan_body(const int* in, int* out, int* bsums, int n) {
    __shared__ int s[SCAN_B];
    int i = blockIdx.x * SCAN_B + threadIdx.x;
    int v = (i < n) ? in[i] : 0;
    s[threadIdx.x] = v;
    __syncthreads();
    #pragma unroll
    for (int off = 1; off < SCAN_B; off <<= 1) {
        int t = (threadIdx.x >= off) ? s[threadIdx.x - off] : 0;
        __syncthreads();
        s[threadIdx.x] += t;
        __syncthreads();
    }
    if (i < n) out[i] = s[threadIdx.x] - v;
    if (bsums && threadIdx.x == SCAN_B - 1) bsums[blockIdx.x] = s[SCAN_B - 1];
}

__global__ void k_scan1() { scan_body(g_counts, g_offs, g_bsums, NRSEG); }
__global__ void k_scan2() { scan_body(g_bsums, g_bsums, nullptr, NB1); }

__global__ void k_scan_add() {
    int i = blockIdx.x * blockDim.x + threadIdx.x;
    if (i < NRSEG) {
        int o = g_offs[i] + g_bsums[i >> 10];
        g_offs[i]   = o;
        g_cursor[i] = o;
    }
    if (i == 0) g_offs[NRSEG] = EE;
}

__global__ void k_fill(const int* __restrict__ node_in,
                       const int* __restrict__ node_out,
                       const int* __restrict__ rel,
                       const float* __restrict__ ew) {
    int i = blockIdx.x * blockDim.x + threadIdx.x;
    if (i >= EE) return;
    int seg = node_out[i] * RR + rel[i];
    int p = atomicAdd(&g_cursor[seg], 1);
    g_edge[p] = make_int2(node_in[i], __float_as_int(ew[i]));
}

// ---------------- fused scatter+GEMM ----------------------------------------
// CTA: 128 nodes x 128 out-cols, virtual K=1024 (14 chunks of segment-sums +
// 2 chunks of x). Per chunk c<14 (rel=c>>1, dhalf=c&1) the CTA PRODUCES its
// 128x64 A-tile (segment sums over CSR edges, fp32 -> bf16 hi/lo) directly in
// smem; B (pre-split weights) arrives via double-buffered cp.async.
// MMA: 3-term bf16 split, fp32 accum (Ah*Bh + Ah*Bl + Al*Bh).
#define TSTRIDE 72
#define TBYTES  (128 * TSTRIDE * 2)          // 18432 per tile
#define STAGEB  (4 * TBYTES)                 // Ah,Al,Bh,Bl = 73728
#define SMTOT   (2 * STAGEB)                 // 147456

__device__ __forceinline__ void cpB(char* sm, int st, int c, int layer, int tid) {
    unsigned base = s2u(sm) + (unsigned)st * STAGEB + 2u * TBYTES;
    const __nv_bfloat16* wh = g_Wh + (size_t)layer * 131072;
    const __nv_bfloat16* wl = g_Wl + (size_t)layer * 131072;
    #pragma unroll
    for (int i = 0; i < 8; i++) {
        int idx = tid + 256 * i;             // 2048 x 16B units (Bh then Bl)
        int arr = idx >> 10;
        int rem = idx & 1023;
        int row = rem >> 3;
        int seg = rem & 7;
        unsigned dst = base + (unsigned)arr * TBYTES + row * 144u + seg * 16u;
        const __nv_bfloat16* src = (arr ? wl : wh) + (size_t)row * 1024 + c * 64 + seg * 8;
        cp16(dst, src);
    }
}

__device__ __forceinline__ void storeAhl(char* Ah, char* Al, int r, int lane,
                                         float vx, float vy) {
    __nv_bfloat16 h0 = __float2bfloat16(vx);
    __nv_bfloat16 h1 = __float2bfloat16(vy);
    __nv_bfloat162 hh; hh.x = h0; hh.y = h1;
    *(unsigned*)(Ah + r * 144 + lane * 4) = *(unsigned*)&hh;
    __nv_bfloat162 ll;
    ll.x = __float2bfloat16(vx - __bfloat162float(h0));
    ll.y = __float2bfloat16(vy - __bfloat162float(h1));
    *(unsigned*)(Al + r * 144 + lane * 4) = *(unsigned*)&ll;
}

// Produce A-tile for chunk c into stage st. Warp w handles rows [w*16, w*16+16).
// Lane covers cols 2*lane, 2*lane+1 of the 64-wide chunk.
__device__ __forceinline__ void produceA(char* sm, int st, int c, int row0,
                                         const float* __restrict__ xin, int tid) {
    char* Ah = sm + st * STAGEB;
    char* Al = Ah + TBYTES;
    int wid = tid >> 5, lane = tid & 31;

    if (c >= 14) {                            // x chunks
        int colb = (c - 14) * 64;
        #pragma unroll 4
        for (int i = 0; i < 16; i++) {
            int r = wid * 16 + i;
            float2 v = *(const float2*)(xin + (size_t)(row0 + r) * 128 + colb + 2 * lane);
            storeAhl(Ah, Al, r, lane, v.x, v.y);
        }
        return;
    }

    int rel  = c >> 1;
    int colb = (c & 1) * 64;
    // preload the 16 segment ranges via lanes (seg stride = RR per row)
    int myb = 0, mye = 0;
    if (lane < 16) {
        int node = row0 + wid * 16 + lane;
        if (node < NN) {
            int sg = node * RR + rel;
            myb = g_offs[sg];
            mye = g_offs[sg + 1];
        }
    }
    for (int i = 0; i < 16; i++) {
        int beg = __shfl_sync(0xffffffffu, myb, i);
        int end = __shfl_sync(0xffffffffu, mye, i);
        float ax = 0.f, ay = 0.f;
        for (int b = beg; b < end; b += 32) {
            int cnt = min(32, end - b);
            int2 ewv = (lane < cnt) ? g_edge[b + lane] : make_int2(0, 0);
            for (int e = 0; e < cnt; e++) {
                int   s = __shfl_sync(0xffffffffu, ewv.x, e);
                float w = __int_as_float(__shfl_sync(0xffffffffu, ewv.y, e));
                float2 v = *(const float2*)(xin + (size_t)s * 128 + colb + 2 * lane);
                ax += v.x * w;
                ay += v.y * w;
            }
        }
        storeAhl(Ah, Al, wid * 16 + i, lane, ax, ay);
    }
}

__global__ void __launch_bounds__(256, 1)
k_gemm(int layer, float* __restrict__ xout_ext) {
    extern __shared__ char sm[];
    __shared__ float s_bias[128];

    int tid  = threadIdx.x;
    int wid  = tid >> 5, lane = tid & 31;
    int wm   = wid & 1;                      // 2 warps in m
    int wn   = wid >> 1;                     // 4 warps in n
    int row0 = blockIdx.x * 128;
    const float* __restrict__ xin = g_x[layer & 1];
    float* __restrict__ xout = xout_ext ? xout_ext : g_x[(layer + 1) & 1];

    if (tid < 128) s_bias[tid] = g_bias[layer * 128 + tid];

    float acc[4][4][4];
    #pragma unroll
    for (int a = 0; a < 4; a++)
        #pragma unroll
        for (int b = 0; b < 4; b++)
            #pragma unroll
            for (int e = 0; e < 4; e++) acc[a][b][e] = 0.f;

    // prologue: B(0), B(1) async; A(0), A(1) produced in-thread
    cpB(sm, 0, 0, layer, tid); cp_commit();
    cpB(sm, 1, 1, layer, tid); cp_commit();
    produceA(sm, 0, 0, row0, xin, tid);
    produceA(sm, 1, 1, row0, xin, tid);

    const int g = lane >> 2, q = lane & 3;
    for (int c = 0; c < 16; ++c) {
        if (c < 15) cp_wait1(); else cp_wait0();   // B(c) resident
        __syncthreads();                            // + A(c) STS visible

        const char* st = sm + (c & 1) * STAGEB;
        const char* Ah = st;
        const char* Al = st + TBYTES;
        const char* Bh = st + 2 * TBYTES;
        const char* Bl = st + 3 * TBYTES;

        #pragma unroll
        for (int ks = 0; ks < 4; ++ks) {
            int k0 = ks * 16 + 2 * q;
            unsigned ah[4][4], al_[4][4], bh[4][2], bl[4][2];
            #pragma unroll
            for (int mt = 0; mt < 4; ++mt) {
                int r = wm * 64 + mt * 16 + g;
                ah[mt][0] = *(const unsigned*)(Ah + r * 144 + k0 * 2);
                ah[mt][1] = *(const unsigned*)(Ah + (r + 8) * 144 + k0 * 2);
                ah[mt][2] = *(const unsigned*)(Ah + r * 144 + (k0 + 8) * 2);
                ah[mt][3] = *(const unsigned*)(Ah + (r + 8) * 144 + (k0 + 8) * 2);
                al_[mt][0] = *(const unsigned*)(Al + r * 144 + k0 * 2);
                al_[mt][1] = *(const unsigned*)(Al + (r + 8) * 144 + k0 * 2);
                al_[mt][2] = *(const unsigned*)(Al + r * 144 + (k0 + 8) * 2);
                al_[mt][3] = *(const unsigned*)(Al + (r + 8) * 144 + (k0 + 8) * 2);
            }
            #pragma unroll
            for (int nt = 0; nt < 4; ++nt) {
                int n = wn * 32 + nt * 8 + g;
                bh[nt][0] = *(const unsigned*)(Bh + n * 144 + k0 * 2);
                bh[nt][1] = *(const unsigned*)(Bh + n * 144 + (k0 + 8) * 2);
                bl[nt][0] = *(const unsigned*)(Bl + n * 144 + k0 * 2);
                bl[nt][1] = *(const unsigned*)(Bl + n * 144 + (k0 + 8) * 2);
            }
            #pragma unroll
            for (int mt = 0; mt < 4; ++mt)
                #pragma unroll
                for (int nt = 0; nt < 4; ++nt) {
                    mma16816(acc[mt][nt], ah[mt],  bh[nt]);
                    mma16816(acc[mt][nt], ah[mt],  bl[nt]);
                    mma16816(acc[mt][nt], al_[mt], bh[nt]);
                }
        }
        __syncthreads();                            // all warps done reading stage
        if (c + 2 < 16) {
            cpB(sm, c & 1, c + 2, layer, tid); cp_commit();
            produceA(sm, c & 1, c + 2, row0, xin, tid);
        }
    }

    // epilogue: bias + relu, fp32 store
    #pragma unroll
    for (int mt = 0; mt < 4; ++mt) {
        int m0 = row0 + wm * 64 + mt * 16 + g;
        #pragma unroll
        for (int nt = 0; nt < 4; ++nt) {
            int col = wn * 32 + nt * 8 + 2 * q;
            float b0 = s_bias[col], b1 = s_bias[col + 1];
            #pragma unroll
            for (int half = 0; half < 2; ++half) {
                int m = m0 + half * 8;
                if (m >= NN) continue;
                float v0 = fmaxf(acc[mt][nt][2 * half]     + b0, 0.f);
                float v1 = fmaxf(acc[mt][nt][2 * half + 1] + b1, 0.f);
                *(float2*)(xout + (size_t)m * 128 + col) = make_float2(v0, v1);
            }
        }
    }
}

// ---------------- graph pooling (node2graph sorted) --------------------------
__global__ void k_segsum(const float* __restrict__ x,
                         const int* __restrict__ n2g,
                         float* __restrict__ out) {
    int d  = threadIdx.x;
    int r0 = blockIdx.x * 512;
    if (r0 >= NN) return;
    int r1 = min(r0 + 512, NN);
    float acc = 0.f;
    int gcur = n2g[r0];
    for (int r = r0; r < r1; ++r) {
        int g = n2g[r];
        if (g != gcur) {
            atomicAdd(&out[gcur * DD + d], acc);
            acc = 0.f; gcur = g;
        }
        acc += x[(size_t)r * DD + d];
    }
    atomicAdd(&out[gcur * DD + d], acc);
}

// ---------------- launch -----------------------------------------------------
extern "C" void kernel_launch(void* const* d_in, const int* in_sizes, int n_in,
                              void* d_out, int out_size) {
    const int*   unit_type   = (const int*)  d_in[0];
    const int*   node_in     = (const int*)  d_in[1];
    const int*   node_out    = (const int*)  d_in[2];
    const int*   relation    = (const int*)  d_in[3];
    const float* edge_weight = (const float*)d_in[4];
    const int*   node2graph  = (const int*)  d_in[5];
    const float* emb         = (const float*)d_in[6];
    const float* W_rel       = (const float*)d_in[7];
    const float* b_rel       = (const float*)d_in[8];
    const float* W_loop      = (const float*)d_in[9];
    const float* b_loop      = (const float*)d_in[10];

    float* out    = (float*)d_out;
    float* out_gf = out;
    float* out_x  = out + GG * DD;

    cudaFuncSetAttribute(k_gemm, cudaFuncAttributeMaxDynamicSharedMemorySize, SMTOT);

    k_init_x<<<(NN * DD + 255) / 256, 256>>>(unit_type, emb);
    k_zero_out<<<(GG * DD + 255) / 256, 256>>>(out_gf);
    k_wconv<<<(3 * 128 * 1024 + 255) / 256, 256>>>(W_rel, W_loop, b_rel, b_loop);

    k_zero_counts<<<(NRSEG + 255) / 256, 256>>>();
    k_hist<<<(EE + 255) / 256, 256>>>(node_out, relation);
    k_scan1<<<NB1, SCAN_B>>>();
    k_scan2<<<1, SCAN_B>>>();
    k_scan_add<<<(NRSEG + 255) / 256, 256>>>();
    k_fill<<<(EE + 255) / 256, 256>>>(node_in, node_out, relation, edge_weight);

    for (int L = 0; L < 3; ++L) {
        float* oext = (L == 2) ? out_x : nullptr;
        k_gemm<<<(NN + 127) / 128, 256, SMTOT>>>(L, oext);
    }

    k_segsum<<<(NN + 511) / 512, 128>>>(out_x, node2graph, out_gf);
}

// round 9
// speedup vs baseline: 2.0309x; 2.0309x over previous
#include <cuda_runtime.h>
#include <cuda_bf16.h>

#define NN 50000
#define NPAD 50048
#define EE 1600000
#define RR 7
#define DD 128
#define GG 64
#define NRSEG (NN * RR)          // 350000
#define SCAN_B 1024
#define NB1 ((NRSEG + SCAN_B - 1) / SCAN_B)

// ---------------- static device scratch ------------------------------------
__device__ float g_x[2][(size_t)NPAD * DD];
__device__ __nv_bfloat16 g_xh[(size_t)NPAD * DD];
__device__ __nv_bfloat16 g_xl[(size_t)NPAD * DD];
__device__ __nv_bfloat16 g_uh[(size_t)NPAD * 896];
__device__ __nv_bfloat16 g_ul[(size_t)NPAD * 896];
__device__ __nv_bfloat16 g_Wh[3 * 128 * 1024];   // [L][n][k] transposed, k-contig
__device__ __nv_bfloat16 g_Wl[3 * 128 * 1024];
__device__ float g_bias[3 * 128];
__device__ int   g_counts[NRSEG];
__device__ int   g_offs[NRSEG + 1];
__device__ int   g_cursor[NRSEG];
__device__ int   g_bsums[SCAN_B];
__device__ int2  g_edge[EE];                     // (src, w-bits), segment-sorted

// ---------------- helpers ----------------------------------------------------
__device__ __forceinline__ unsigned s2u(const void* p) {
    unsigned a;
    asm("{ .reg .u64 t; cvta.to.shared.u64 t, %1; cvt.u32.u64 %0, t; }" : "=r"(a) : "l"(p));
    return a;
}
__device__ __forceinline__ void cp16(unsigned dst, const void* src) {
    asm volatile("cp.async.cg.shared.global [%0], [%1], 16;" :: "r"(dst), "l"(src) : "memory");
}
__device__ __forceinline__ void cp_commit() { asm volatile("cp.async.commit_group;" ::: "memory"); }
__device__ __forceinline__ void cp_wait1()  { asm volatile("cp.async.wait_group 1;" ::: "memory"); }
__device__ __forceinline__ void cp_wait0()  { asm volatile("cp.async.wait_group 0;" ::: "memory"); }
__device__ __forceinline__ void stcs8(void* p, unsigned x, unsigned y) {
    asm volatile("st.global.cs.v2.b32 [%0], {%1, %2};" :: "l"(p), "r"(x), "r"(y) : "memory");
}

__device__ __forceinline__ void mma16816(float* c, const unsigned* a, const unsigned* b) {
    asm volatile(
        "mma.sync.aligned.m16n8k16.row.col.f32.bf16.bf16.f32 "
        "{%0,%1,%2,%3}, {%4,%5,%6,%7}, {%8,%9}, {%0,%1,%2,%3};"
        : "+f"(c[0]), "+f"(c[1]), "+f"(c[2]), "+f"(c[3])
        : "r"(a[0]), "r"(a[1]), "r"(a[2]), "r"(a[3]), "r"(b[0]), "r"(b[1]));
}

// ---------------- init: x0 = emb[unit_type] + bf16 split ---------------------
__global__ void k_init_x(const int* __restrict__ unit_type,
                         const float* __restrict__ emb) {
    int i = blockIdx.x * blockDim.x + threadIdx.x;
    if (i >= NN * DD) return;
    int n = i >> 7, d = i & 127;
    float v = emb[unit_type[n] * DD + d];
    g_x[0][i] = v;
    __nv_bfloat16 h = __float2bfloat16(v);
    g_xh[i] = h;
    g_xl[i] = __float2bfloat16(v - __bfloat162float(h));
}

__global__ void k_zero_out(float* __restrict__ out) {
    int i = blockIdx.x * blockDim.x + threadIdx.x;
    if (i < GG * DD) out[i] = 0.0f;
}

// ---------------- weight transpose + bf16 split ------------------------------
__global__ void k_wconv(const float* __restrict__ Wrel,
                        const float* __restrict__ Wloop,
                        const float* __restrict__ brel,
                        const float* __restrict__ bloop) {
    int idx = blockIdx.x * blockDim.x + threadIdx.x;
    if (idx < 3 * 128 * 1024) {
        int L = idx >> 17;
        int r = idx & 131071;
        int n = r >> 10;
        int k = r & 1023;
        float w = (k < 896) ? Wrel[((size_t)L * 896 + k) * 128 + n]
                            : Wloop[((size_t)L * 128 + (k - 896)) * 128 + n];
        __nv_bfloat16 h = __float2bfloat16(w);
        g_Wh[idx] = h;
        g_Wl[idx] = __float2bfloat16(w - __bfloat162float(h));
    }
    if (idx < 3 * 128) g_bias[idx] = brel[idx] + bloop[idx];
}

// ---------------- CSR build --------------------------------------------------
__global__ void k_zero_counts() {
    int i = blockIdx.x * blockDim.x + threadIdx.x;
    if (i < NRSEG) g_counts[i] = 0;
}

__global__ void k_hist(const int* __restrict__ node_out,
                       const int* __restrict__ rel) {
    int i = blockIdx.x * blockDim.x + threadIdx.x;
    if (i < EE) atomicAdd(&g_counts[node_out[i] * RR + rel[i]], 1);
}

__device__ __forceinline__ void scan_body(const int* in, int* out, int* bsums, int n) {
    __shared__ int s[SCAN_B];
    int i = blockIdx.x * SCAN_B + threadIdx.x;
    int v = (i < n) ? in[i] : 0;
    s[threadIdx.x] = v;
    __syncthreads();
    #pragma unroll
    for (int off = 1; off < SCAN_B; off <<= 1) {
        int t = (threadIdx.x >= off) ? s[threadIdx.x - off] : 0;
        __syncthreads();
        s[threadIdx.x] += t;
        __syncthreads();
    }
    if (i < n) out[i] = s[threadIdx.x] - v;
    if (bsums && threadIdx.x == SCAN_B - 1) bsums[blockIdx.x] = s[SCAN_B - 1];
}

__global__ void k_scan1() { scan_body(g_counts, g_offs, g_bsums, NRSEG); }
__global__ void k_scan2() { scan_body(g_bsums, g_bsums, nullptr, NB1); }

__global__ void k_scan_add() {
    int i = blockIdx.x * blockDim.x + threadIdx.x;
    if (i < NRSEG) {
        int o = g_offs[i] + g_bsums[i >> 10];
        g_offs[i]   = o;
        g_cursor[i] = o;
    }
    if (i == 0) g_offs[NRSEG] = EE;
}

__global__ void k_fill(const int* __restrict__ node_in,
                       const int* __restrict__ node_out,
                       const int* __restrict__ rel,
                       const float* __restrict__ ew) {
    int i = blockIdx.x * blockDim.x + threadIdx.x;
    if (i >= EE) return;
    int seg = node_out[i] * RR + rel[i];
    int p = atomicAdd(&g_cursor[seg], 1);
    g_edge[p] = make_int2(node_in[i], __float_as_int(ew[i]));
}

// ---------------- per-layer edge scatter -> bf16 hi/lo -----------------------
// One warp per segment. Edge records prefetched one ahead (shortens the
// per-edge dependent chain); upd writes use st.global.cs so the 179MB write
// stream doesn't evict x (25.6MB) from L2 — gathers stay L2-resident.
__global__ void k_scatter(int layer) {
    int gw   = (blockIdx.x * blockDim.x + threadIdx.x) >> 5;
    int lane = threadIdx.x & 31;
    if (gw >= NRSEG) return;
    const float4* __restrict__ xv = (const float4*)g_x[layer & 1];
    int beg = g_offs[gw], end = g_offs[gw + 1];
    float4 acc = make_float4(0.f, 0.f, 0.f, 0.f);
    int2 nxt = (beg < end) ? g_edge[beg] : make_int2(0, 0);
    for (int e = beg; e < end; ++e) {
        int2 cur = nxt;
        if (e + 1 < end) nxt = g_edge[e + 1];
        float w = __int_as_float(cur.y);
        float4 v = xv[(size_t)cur.x * 32 + lane];
        acc.x += v.x * w; acc.y += v.y * w;
        acc.z += v.z * w; acc.w += v.w * w;
    }
    size_t o = (size_t)gw * 128 + lane * 4;
    __nv_bfloat16 h0 = __float2bfloat16(acc.x);
    __nv_bfloat16 h1 = __float2bfloat16(acc.y);
    __nv_bfloat16 h2 = __float2bfloat16(acc.z);
    __nv_bfloat16 h3 = __float2bfloat16(acc.w);
    __nv_bfloat162 a, b; a.x = h0; a.y = h1; b.x = h2; b.y = h3;
    __nv_bfloat162 c, d;
    c.x = __float2bfloat16(acc.x - __bfloat162float(h0));
    c.y = __float2bfloat16(acc.y - __bfloat162float(h1));
    d.x = __float2bfloat16(acc.z - __bfloat162float(h2));
    d.y = __float2bfloat16(acc.w - __bfloat162float(h3));
    stcs8(g_uh + o, *(unsigned*)&a, *(unsigned*)&b);
    stcs8(g_ul + o, *(unsigned*)&c, *(unsigned*)&d);
}

// ---------------- mma.sync GEMM: h = [upd|x] @ W + b, relu -------------------
// CTA: 128 rows x 128 cols, K=1024 (896 upd + 128 x), BK=64, double-buffered
// cp.async. 3-term bf16 split into fp32 accum: Ah*Bh + Ah*Bl + Al*Bh.
// Smem tiles [row][72 bf16] (144B stride) -> conflict-free 32b fragment loads.
#define TSTRIDE 72
#define TBYTES  (128 * TSTRIDE * 2)          // 18432 per tile
#define STAGEB  (4 * TBYTES)                 // Ah,Al,Bh,Bl = 73728
#define SMTOT   (2 * STAGEB)                 // 147456

__device__ __forceinline__ void load_chunk(char* sm, int stage, int c,
                                           int row0, int layer, int tid) {
    unsigned base = s2u(sm) + (unsigned)stage * STAGEB;
    const __nv_bfloat16* wh = g_Wh + (size_t)layer * 131072;
    const __nv_bfloat16* wl = g_Wl + (size_t)layer * 131072;
    #pragma unroll
    for (int i = 0; i < 16; i++) {
        int idx = tid + 256 * i;             // 4096 x 16B units
        int arr = idx >> 10;
        int rem = idx & 1023;
        int row = rem >> 3;
        int seg = rem & 7;
        unsigned dst = base + (unsigned)arr * TBYTES + row * 144u + seg * 16u;
        const __nv_bfloat16* src;
        if (arr < 2) {                        // A (hi / lo)
            if (c < 14) {
                size_t o = (size_t)(row0 + row) * 896 + c * 64 + seg * 8;
                src = (arr == 0 ? g_uh : g_ul) + o;
            } else {
                size_t o = (size_t)(row0 + row) * 128 + (c - 14) * 64 + seg * 8;
                src = (arr == 0 ? g_xh : g_xl) + o;
            }
        } else {                              // B (hi / lo)
            size_t o = (size_t)row * 1024 + c * 64 + seg * 8;
            src = (arr == 2 ? wh : wl) + o;
        }
        cp16(dst, src);
    }
}

__global__ void __launch_bounds__(256, 1)
k_gemm(int layer, float* __restrict__ xout_ext, int dosplit) {
    extern __shared__ char sm[];
    __shared__ float s_bias[128];

    int tid  = threadIdx.x;
    int wid  = tid >> 5, lane = tid & 31;
    int wm   = wid & 1;                      // 2 warps in m
    int wn   = wid >> 1;                     // 4 warps in n
    int row0 = blockIdx.x * 128;
    float* __restrict__ xout = xout_ext ? xout_ext : g_x[(layer + 1) & 1];

    if (tid < 128) s_bias[tid] = g_bias[layer * 128 + tid];

    float acc[4][4][4];
    #pragma unroll
    for (int a = 0; a < 4; a++)
        #pragma unroll
        for (int b = 0; b < 4; b++)
            #pragma unroll
            for (int e = 0; e < 4; e++) acc[a][b][e] = 0.f;

    load_chunk(sm, 0, 0, row0, layer, tid);
    cp_commit();

    const int g = lane >> 2, q = lane & 3;
    for (int c = 0; c < 16; ++c) {
        if (c < 15) {
            load_chunk(sm, (c + 1) & 1, c + 1, row0, layer, tid);
            cp_commit();
            cp_wait1();
        } else {
            cp_wait0();
        }
        __syncthreads();

        const char* st = sm + (c & 1) * STAGEB;
        const char* Ah = st;
        const char* Al = st + TBYTES;
        const char* Bh = st + 2 * TBYTES;
        const char* Bl = st + 3 * TBYTES;

        #pragma unroll
        for (int ks = 0; ks < 4; ++ks) {
            int k0 = ks * 16 + 2 * q;        // bf16 element index in row
            unsigned ah[4][4], al_[4][4], bh[4][2], bl[4][2];
            #pragma unroll
            for (int mt = 0; mt < 4; ++mt) {
                int r = wm * 64 + mt * 16 + g;
                ah[mt][0] = *(const unsigned*)(Ah + r * 144 + k0 * 2);
                ah[mt][1] = *(const unsigned*)(Ah + (r + 8) * 144 + k0 * 2);
                ah[mt][2] = *(const unsigned*)(Ah + r * 144 + (k0 + 8) * 2);
                ah[mt][3] = *(const unsigned*)(Ah + (r + 8) * 144 + (k0 + 8) * 2);
                al_[mt][0] = *(const unsigned*)(Al + r * 144 + k0 * 2);
                al_[mt][1] = *(const unsigned*)(Al + (r + 8) * 144 + k0 * 2);
                al_[mt][2] = *(const unsigned*)(Al + r * 144 + (k0 + 8) * 2);
                al_[mt][3] = *(const unsigned*)(Al + (r + 8) * 144 + (k0 + 8) * 2);
            }
            #pragma unroll
            for (int nt = 0; nt < 4; ++nt) {
                int n = wn * 32 + nt * 8 + g;
                bh[nt][0] = *(const unsigned*)(Bh + n * 144 + k0 * 2);
                bh[nt][1] = *(const unsigned*)(Bh + n * 144 + (k0 + 8) * 2);
                bl[nt][0] = *(const unsigned*)(Bl + n * 144 + k0 * 2);
                bl[nt][1] = *(const unsigned*)(Bl + n * 144 + (k0 + 8) * 2);
            }
            #pragma unroll
            for (int mt = 0; mt < 4; ++mt)
                #pragma unroll
                for (int nt = 0; nt < 4; ++nt) {
                    mma16816(acc[mt][nt], ah[mt],  bh[nt]);
                    mma16816(acc[mt][nt], ah[mt],  bl[nt]);
                    mma16816(acc[mt][nt], al_[mt], bh[nt]);
                }
        }
        __syncthreads();
    }

    // epilogue: bias + relu, fp32 store (+ bf16 split for next layer)
    #pragma unroll
    for (int mt = 0; mt < 4; ++mt) {
        int m0 = row0 + wm * 64 + mt * 16 + g;
        #pragma unroll
        for (int nt = 0; nt < 4; ++nt) {
            int col = wn * 32 + nt * 8 + 2 * q;
            float b0 = s_bias[col], b1 = s_bias[col + 1];
            #pragma unroll
            for (int half = 0; half < 2; ++half) {
                int m = m0 + half * 8;
                if (m >= NN) continue;
                float v0 = fmaxf(acc[mt][nt][2 * half]     + b0, 0.f);
                float v1 = fmaxf(acc[mt][nt][2 * half + 1] + b1, 0.f);
                float2* dst = (float2*)(xout + (size_t)m * 128 + col);
                *dst = make_float2(v0, v1);
                if (dosplit) {
                    __nv_bfloat16 h0 = __float2bfloat16(v0);
                    __nv_bfloat16 h1 = __float2bfloat16(v1);
                    __nv_bfloat162 hh; hh.x = h0; hh.y = h1;
                    *(unsigned*)(g_xh + (size_t)m * 128 + col) = *(unsigned*)&hh;
                    __nv_bfloat162 ll;
                    ll.x = __float2bfloat16(v0 - __bfloat162float(h0));
                    ll.y = __float2bfloat16(v1 - __bfloat162float(h1));
                    *(unsigned*)(g_xl + (size_t)m * 128 + col) = *(unsigned*)&ll;
                }
            }
        }
    }
}

// ---------------- graph pooling (node2graph sorted) --------------------------
__global__ void k_segsum(const float* __restrict__ x,
                         const int* __restrict__ n2g,
                         float* __restrict__ out) {
    int d  = threadIdx.x;
    int r0 = blockIdx.x * 512;
    if (r0 >= NN) return;
    int r1 = min(r0 + 512, NN);
    float acc = 0.f;
    int gcur = n2g[r0];
    for (int r = r0; r < r1; ++r) {
        int g = n2g[r];
        if (g != gcur) {
            atomicAdd(&out[gcur * DD + d], acc);
            acc = 0.f; gcur = g;
        }
        acc += x[(size_t)r * DD + d];
    }
    atomicAdd(&out[gcur * DD + d], acc);
}

// ---------------- launch -----------------------------------------------------
extern "C" void kernel_launch(void* const* d_in, const int* in_sizes, int n_in,
                              void* d_out, int out_size) {
    const int*   unit_type   = (const int*)  d_in[0];
    const int*   node_in     = (const int*)  d_in[1];
    const int*   node_out    = (const int*)  d_in[2];
    const int*   relation    = (const int*)  d_in[3];
    const float* edge_weight = (const float*)d_in[4];
    const int*   node2graph  = (const int*)  d_in[5];
    const float* emb         = (const float*)d_in[6];
    const float* W_rel       = (const float*)d_in[7];
    const float* b_rel       = (const float*)d_in[8];
    const float* W_loop      = (const float*)d_in[9];
    const float* b_loop      = (const float*)d_in[10];

    float* out    = (float*)d_out;
    float* out_gf = out;
    float* out_x  = out + GG * DD;

    cudaFuncSetAttribute(k_gemm, cudaFuncAttributeMaxDynamicSharedMemorySize, SMTOT);

    k_init_x<<<(NN * DD + 255) / 256, 256>>>(unit_type, emb);
    k_zero_out<<<(GG * DD + 255) / 256, 256>>>(out_gf);
    k_wconv<<<(3 * 128 * 1024 + 255) / 256, 256>>>(W_rel, W_loop, b_rel, b_loop);

    k_zero_counts<<<(NRSEG + 255) / 256, 256>>>();
    k_hist<<<(EE + 255) / 256, 256>>>(node_out, relation);
    k_scan1<<<NB1, SCAN_B>>>();
    k_scan2<<<1, SCAN_B>>>();
    k_scan_add<<<(NRSEG + 255) / 256, 256>>>();
    k_fill<<<(EE + 255) / 256, 256>>>(node_in, node_out, relation, edge_weight);

    for (int L = 0; L < 3; ++L) {
        k_scatter<<<(NRSEG * 32 + 255) / 256, 256>>>(L);
        float* oext = (L == 2) ? out_x : nullptr;
        k_gemm<<<(NN + 127) / 128, 256, SMTOT>>>(L, oext, (L < 2) ? 1 : 0);
    }

    k_segsum<<<(NN + 511) / 512, 128>>>(out_x, node2graph, out_gf);
}

// round 11
// speedup vs baseline: 2.1499x; 1.0586x over previous
#include <cuda_runtime.h>
#include <cuda_bf16.h>

#define NN 50000
#define NPAD 50048
#define EE 1600000
#define RR 7
#define DD 128
#define GG 64
#define NRSEG (NN * RR)          // 350000
#define SCAN_B 1024
#define NB1 ((NRSEG + SCAN_B - 1) / SCAN_B)   // 342

// ---------------- static device scratch ------------------------------------
__device__ float g_x[2][(size_t)NPAD * DD];
__device__ __nv_bfloat16 g_xh[(size_t)NPAD * DD];
__device__ __nv_bfloat16 g_xl[(size_t)NPAD * DD];
__device__ __nv_bfloat16 g_uh[(size_t)NPAD * 896];
__device__ __nv_bfloat16 g_ul[(size_t)NPAD * 896];
__device__ __nv_bfloat16 g_Wh[3 * 128 * 1024];   // [L][n][k] transposed, k-contig
__device__ __nv_bfloat16 g_Wl[3 * 128 * 1024];
__device__ float g_bias[3 * 128];
__device__ int   g_counts[NRSEG];
__device__ int   g_offs[NRSEG + 1];
__device__ int   g_cursor[NRSEG];
__device__ unsigned long long g_scanstate[NB1];  // (sum<<2)|flag: 0 inv,1 agg,2 incl
__device__ int2  g_edge[EE];                     // (src, w-bits), segment-sorted

// ---------------- helpers ----------------------------------------------------
__device__ __forceinline__ unsigned s2u(const void* p) {
    unsigned a;
    asm("{ .reg .u64 t; cvta.to.shared.u64 t, %1; cvt.u32.u64 %0, t; }" : "=r"(a) : "l"(p));
    return a;
}
__device__ __forceinline__ void cp16(unsigned dst, const void* src) {
    asm volatile("cp.async.cg.shared.global [%0], [%1], 16;" :: "r"(dst), "l"(src) : "memory");
}
__device__ __forceinline__ unsigned long long mk_evict_first() {
    unsigned long long p;
    asm("createpolicy.fractional.L2::evict_first.b64 %0, 1.0;" : "=l"(p));
    return p;
}
__device__ __forceinline__ unsigned long long mk_evict_last() {
    unsigned long long p;
    asm("createpolicy.fractional.L2::evict_last.b64 %0, 1.0;" : "=l"(p));
    return p;
}
__device__ __forceinline__ void cp16_ef(unsigned dst, const void* src,
                                        unsigned long long pol) {
    asm volatile("cp.async.cg.shared.global.L2::cache_hint [%0], [%1], 16, %2;"
                 :: "r"(dst), "l"(src), "l"(pol) : "memory");
}
__device__ __forceinline__ void cp_commit() { asm volatile("cp.async.commit_group;" ::: "memory"); }
__device__ __forceinline__ void cp_wait1()  { asm volatile("cp.async.wait_group 1;" ::: "memory"); }
__device__ __forceinline__ void cp_wait0()  { asm volatile("cp.async.wait_group 0;" ::: "memory"); }
__device__ __forceinline__ void stcs8(void* p, unsigned x, unsigned y) {
    asm volatile("st.global.cs.v2.b32 [%0], {%1, %2};" :: "l"(p), "r"(x), "r"(y) : "memory");
}
// evict_last gather via cache-hint operand form (inline .L2::evict_last
// modifier is rejected for v4.f32 by this ptxas; the policy-operand form works)
__device__ __forceinline__ float4 ldg_el(const float4* p, unsigned long long pol) {
    float4 v;
    asm volatile("ld.global.nc.L2::cache_hint.v4.f32 {%0,%1,%2,%3}, [%4], %5;"
                 : "=f"(v.x), "=f"(v.y), "=f"(v.z), "=f"(v.w) : "l"(p), "l"(pol));
    return v;
}
__device__ __forceinline__ void st_rel(unsigned long long* p, unsigned long long v) {
    asm volatile("st.release.gpu.u64 [%0], %1;" :: "l"(p), "l"(v) : "memory");
}
__device__ __forceinline__ unsigned long long ld_acq(unsigned long long* p) {
    unsigned long long v;
    asm volatile("ld.acquire.gpu.u64 %0, [%1];" : "=l"(v) : "l"(p) : "memory");
    return v;
}

__device__ __forceinline__ void mma16816(float* c, const unsigned* a, const unsigned* b) {
    asm volatile(
        "mma.sync.aligned.m16n8k16.row.col.f32.bf16.bf16.f32 "
        "{%0,%1,%2,%3}, {%4,%5,%6,%7}, {%8,%9}, {%0,%1,%2,%3};"
        : "+f"(c[0]), "+f"(c[1]), "+f"(c[2]), "+f"(c[3])
        : "r"(a[0]), "r"(a[1]), "r"(a[2]), "r"(a[3]), "r"(b[0]), "r"(b[1]));
}

// ---------------- fused setup (launch 0) ------------------------------------
// init x0 + splits, weight transpose + split, bias, zero counters/out/scanstate
__global__ void k_setup(const int* __restrict__ unit_type,
                        const float* __restrict__ emb,
                        const float* __restrict__ Wrel,
                        const float* __restrict__ Wloop,
                        const float* __restrict__ brel,
                        const float* __restrict__ bloop,
                        float* __restrict__ out_gf) {
    int i = blockIdx.x * blockDim.x + threadIdx.x;
    if (i < NN * DD) {
        int n = i >> 7, d = i & 127;
        float v = emb[unit_type[n] * DD + d];
        g_x[0][i] = v;
        __nv_bfloat16 h = __float2bfloat16(v);
        g_xh[i] = h;
        g_xl[i] = __float2bfloat16(v - __bfloat162float(h));
    }
    if (i < 3 * 128 * 1024) {
        int L = i >> 17;
        int r = i & 131071;
        int n = r >> 10;
        int k = r & 1023;
        float w = (k < 896) ? Wrel[((size_t)L * 896 + k) * 128 + n]
                            : Wloop[((size_t)L * 128 + (k - 896)) * 128 + n];
        __nv_bfloat16 h = __float2bfloat16(w);
        g_Wh[i] = h;
        g_Wl[i] = __float2bfloat16(w - __bfloat162float(h));
    }
    if (i < NRSEG) g_counts[i] = 0;
    if (i < NB1)   g_scanstate[i] = 0ull;
    if (i < 3 * 128) g_bias[i] = brel[i] + bloop[i];
    if (i < GG * DD) out_gf[i] = 0.0f;
}

// ---------------- CSR build --------------------------------------------------
__global__ void k_hist(const int* __restrict__ node_out,
                       const int* __restrict__ rel) {
    int i = blockIdx.x * blockDim.x + threadIdx.x;
    if (i < EE) atomicAdd(&g_counts[node_out[i] * RR + rel[i]], 1);
}

// single-kernel exclusive scan over g_counts (decoupled lookback)
__global__ void k_scan() {
    __shared__ int s[SCAN_B];
    __shared__ int s_prefix;
    int bid = blockIdx.x, tid = threadIdx.x;
    int i = bid * SCAN_B + tid;
    int v = (i < NRSEG) ? g_counts[i] : 0;
    s[tid] = v;
    __syncthreads();
    #pragma unroll
    for (int off = 1; off < SCAN_B; off <<= 1) {
        int t = (tid >= off) ? s[tid - off] : 0;
        __syncthreads();
        s[tid] += t;
        __syncthreads();
    }
    int incl  = s[tid];
    int total = s[SCAN_B - 1];

    if (tid == 0) {
        if (bid == 0) {
            st_rel(&g_scanstate[0], ((unsigned long long)total << 2) | 2ull);
            s_prefix = 0;
        } else {
            st_rel(&g_scanstate[bid], ((unsigned long long)total << 2) | 1ull);
            int prefix = 0, j = bid - 1;
            while (true) {
                unsigned long long st = ld_acq(&g_scanstate[j]);
                unsigned f = (unsigned)(st & 3ull);
                if (f == 2u) { prefix += (int)(st >> 2); break; }
                if (f == 1u) { prefix += (int)(st >> 2); --j; }
            }
            st_rel(&g_scanstate[bid],
                   ((unsigned long long)(prefix + total) << 2) | 2ull);
            s_prefix = prefix;
        }
    }
    __syncthreads();
    if (i < NRSEG) {
        int excl = s_prefix + incl - v;
        g_offs[i]   = excl;
        g_cursor[i] = excl;
    }
    if (i == 0) g_offs[NRSEG] = EE;
}

__global__ void k_fill(const int* __restrict__ node_in,
                       const int* __restrict__ node_out,
                       const int* __restrict__ rel,
                       const float* __restrict__ ew) {
    int i = blockIdx.x * blockDim.x + threadIdx.x;
    if (i >= EE) return;
    int seg = node_out[i] * RR + rel[i];
    int p = atomicAdd(&g_cursor[seg], 1);
    g_edge[p] = make_int2(node_in[i], __float_as_int(ew[i]));
}

// ---------------- per-layer edge scatter -> bf16 hi/lo -----------------------
// One warp per segment; 2-wide edge unroll (two independent gather chains);
// x gathers use evict_last policy (x reused ~32x, keep in L2); upd writes st.cs.
__global__ void k_scatter(int layer) {
    int gw   = (blockIdx.x * blockDim.x + threadIdx.x) >> 5;
    int lane = threadIdx.x & 31;
    if (gw >= NRSEG) return;
    const float4* __restrict__ xv = (const float4*)g_x[layer & 1];
    unsigned long long pol = mk_evict_last();
    int beg = g_offs[gw], end = g_offs[gw + 1];
    float4 a0 = make_float4(0.f, 0.f, 0.f, 0.f);
    float4 a1 = make_float4(0.f, 0.f, 0.f, 0.f);
    int e = beg;
    for (; e + 2 <= end; e += 2) {
        int2 e0 = g_edge[e];
        int2 e1 = g_edge[e + 1];
        float4 v0 = ldg_el(xv + (size_t)e0.x * 32 + lane, pol);
        float4 v1 = ldg_el(xv + (size_t)e1.x * 32 + lane, pol);
        float w0 = __int_as_float(e0.y);
        float w1 = __int_as_float(e1.y);
        a0.x += v0.x * w0; a0.y += v0.y * w0; a0.z += v0.z * w0; a0.w += v0.w * w0;
        a1.x += v1.x * w1; a1.y += v1.y * w1; a1.z += v1.z * w1; a1.w += v1.w * w1;
    }
    if (e < end) {
        int2 e0 = g_edge[e];
        float4 v0 = ldg_el(xv + (size_t)e0.x * 32 + lane, pol);
        float w0 = __int_as_float(e0.y);
        a0.x += v0.x * w0; a0.y += v0.y * w0; a0.z += v0.z * w0; a0.w += v0.w * w0;
    }
    float4 acc = make_float4(a0.x + a1.x, a0.y + a1.y, a0.z + a1.z, a0.w + a1.w);

    size_t o = (size_t)gw * 128 + lane * 4;
    __nv_bfloat16 h0 = __float2bfloat16(acc.x);
    __nv_bfloat16 h1 = __float2bfloat16(acc.y);
    __nv_bfloat16 h2 = __float2bfloat16(acc.z);
    __nv_bfloat16 h3 = __float2bfloat16(acc.w);
    __nv_bfloat162 a, b; a.x = h0; a.y = h1; b.x = h2; b.y = h3;
    __nv_bfloat162 c, d;
    c.x = __float2bfloat16(acc.x - __bfloat162float(h0));
    c.y = __float2bfloat16(acc.y - __bfloat162float(h1));
    d.x = __float2bfloat16(acc.z - __bfloat162float(h2));
    d.y = __float2bfloat16(acc.w - __bfloat162float(h3));
    stcs8(g_uh + o, *(unsigned*)&a, *(unsigned*)&b);
    stcs8(g_ul + o, *(unsigned*)&c, *(unsigned*)&d);
}

// ---------------- mma.sync GEMM: h = [upd|x] @ W + b, relu -------------------
// CTA: 128 rows x 128 cols, K=1024 (896 upd + 128 x), BK=64, double-buffered
// cp.async. 3-term bf16 split into fp32 accum: Ah*Bh + Ah*Bl + Al*Bh.
// A tiles (read-exactly-once) use L2::evict_first so the 358MB/layer stream
// does NOT evict x / edges from L2 (keeps scatter gathers L2-resident).
#define TSTRIDE 72
#define TBYTES  (128 * TSTRIDE * 2)          // 18432 per tile
#define STAGEB  (4 * TBYTES)                 // Ah,Al,Bh,Bl = 73728
#define SMTOT   (2 * STAGEB)                 // 147456

__device__ __forceinline__ void load_chunk(char* sm, int stage, int c,
                                           int row0, int layer, int tid,
                                           unsigned long long pol) {
    unsigned base = s2u(sm) + (unsigned)stage * STAGEB;
    const __nv_bfloat16* wh = g_Wh + (size_t)layer * 131072;
    const __nv_bfloat16* wl = g_Wl + (size_t)layer * 131072;
    #pragma unroll
    for (int i = 0; i < 16; i++) {
        int idx = tid + 256 * i;             // 4096 x 16B units
        int arr = idx >> 10;
        int rem = idx & 1023;
        int row = rem >> 3;
        int seg = rem & 7;
        unsigned dst = base + (unsigned)arr * TBYTES + row * 144u + seg * 16u;
        if (arr < 2) {                        // A (hi / lo): evict-first stream
            const __nv_bfloat16* src;
            if (c < 14) {
                size_t o = (size_t)(row0 + row) * 896 + c * 64 + seg * 8;
                src = (arr == 0 ? g_uh : g_ul) + o;
            } else {
                size_t o = (size_t)(row0 + row) * 128 + (c - 14) * 64 + seg * 8;
                src = (arr == 0 ? g_xh : g_xl) + o;
            }
            cp16_ef(dst, src, pol);
        } else {                              // B (hi / lo): small, keep cached
            size_t o = (size_t)row * 1024 + c * 64 + seg * 8;
            cp16(dst, (arr == 2 ? wh : wl) + o);
        }
    }
}

__global__ void __launch_bounds__(256, 1)
k_gemm(int layer, float* __restrict__ xout_ext, int dosplit) {
    extern __shared__ char sm[];
    __shared__ float s_bias[128];

    int tid  = threadIdx.x;
    int wid  = tid >> 5, lane = tid & 31;
    int wm   = wid & 1;                      // 2 warps in m
    int wn   = wid >> 1;                     // 4 warps in n
    int row0 = blockIdx.x * 128;
    float* __restrict__ xout = xout_ext ? xout_ext : g_x[(layer + 1) & 1];
    unsigned long long pol = mk_evict_first();

    if (tid < 128) s_bias[tid] = g_bias[layer * 128 + tid];

    float acc[4][4][4];
    #pragma unroll
    for (int a = 0; a < 4; a++)
        #pragma unroll
        for (int b = 0; b < 4; b++)
            #pragma unroll
            for (int e = 0; e < 4; e++) acc[a][b][e] = 0.f;

    load_chunk(sm, 0, 0, row0, layer, tid, pol);
    cp_commit();

    const int g = lane >> 2, q = lane & 3;
    for (int c = 0; c < 16; ++c) {
        if (c < 15) {
            load_chunk(sm, (c + 1) & 1, c + 1, row0, layer, tid, pol);
            cp_commit();
            cp_wait1();
        } else {
            cp_wait0();
        }
        __syncthreads();

        const char* st = sm + (c & 1) * STAGEB;
        const char* Ah = st;
        const char* Al = st + TBYTES;
        const char* Bh = st + 2 * TBYTES;
        const char* Bl = st + 3 * TBYTES;

        #pragma unroll
        for (int ks = 0; ks < 4; ++ks) {
            int k0 = ks * 16 + 2 * q;        // bf16 element index in row
            unsigned ah[4][4], al_[4][4], bh[4][2], bl[4][2];
            #pragma unroll
            for (int mt = 0; mt < 4; ++mt) {
                int r = wm * 64 + mt * 16 + g;
                ah[mt][0] = *(const unsigned*)(Ah + r * 144 + k0 * 2);
                ah[mt][1] = *(const unsigned*)(Ah + (r + 8) * 144 + k0 * 2);
                ah[mt][2] = *(const unsigned*)(Ah + r * 144 + (k0 + 8) * 2);
                ah[mt][3] = *(const unsigned*)(Ah + (r + 8) * 144 + (k0 + 8) * 2);
                al_[mt][0] = *(const unsigned*)(Al + r * 144 + k0 * 2);
                al_[mt][1] = *(const unsigned*)(Al + (r + 8) * 144 + k0 * 2);
                al_[mt][2] = *(const unsigned*)(Al + r * 144 + (k0 + 8) * 2);
                al_[mt][3] = *(const unsigned*)(Al + (r + 8) * 144 + (k0 + 8) * 2);
            }
            #pragma unroll
            for (int nt = 0; nt < 4; ++nt) {
                int n = wn * 32 + nt * 8 + g;
                bh[nt][0] = *(const unsigned*)(Bh + n * 144 + k0 * 2);
                bh[nt][1] = *(const unsigned*)(Bh + n * 144 + (k0 + 8) * 2);
                bl[nt][0] = *(const unsigned*)(Bl + n * 144 + k0 * 2);
                bl[nt][1] = *(const unsigned*)(Bl + n * 144 + (k0 + 8) * 2);
            }
            #pragma unroll
            for (int mt = 0; mt < 4; ++mt)
                #pragma unroll
                for (int nt = 0; nt < 4; ++nt) {
                    mma16816(acc[mt][nt], ah[mt],  bh[nt]);
                    mma16816(acc[mt][nt], ah[mt],  bl[nt]);
                    mma16816(acc[mt][nt], al_[mt], bh[nt]);
                }
        }
        __syncthreads();
    }

    // epilogue: bias + relu, fp32 store (+ bf16 split for next layer)
    #pragma unroll
    for (int mt = 0; mt < 4; ++mt) {
        int m0 = row0 + wm * 64 + mt * 16 + g;
        #pragma unroll
        for (int nt = 0; nt < 4; ++nt) {
            int col = wn * 32 + nt * 8 + 2 * q;
            float b0 = s_bias[col], b1 = s_bias[col + 1];
            #pragma unroll
            for (int half = 0; half < 2; ++half) {
                int m = m0 + half * 8;
                if (m >= NN) continue;
                float v0 = fmaxf(acc[mt][nt][2 * half]     + b0, 0.f);
                float v1 = fmaxf(acc[mt][nt][2 * half + 1] + b1, 0.f);
                float2* dst = (float2*)(xout + (size_t)m * 128 + col);
                *dst = make_float2(v0, v1);
                if (dosplit) {
                    __nv_bfloat16 h0 = __float2bfloat16(v0);
                    __nv_bfloat16 h1 = __float2bfloat16(v1);
                    __nv_bfloat162 hh; hh.x = h0; hh.y = h1;
                    *(unsigned*)(g_xh + (size_t)m * 128 + col) = *(unsigned*)&hh;
                    __nv_bfloat162 ll;
                    ll.x = __float2bfloat16(v0 - __bfloat162float(h0));
                    ll.y = __float2bfloat16(v1 - __bfloat162float(h1));
                    *(unsigned*)(g_xl + (size_t)m * 128 + col) = *(unsigned*)&ll;
                }
            }
        }
    }
}

// ---------------- graph pooling (node2graph sorted) --------------------------
__global__ void k_segsum(const float* __restrict__ x,
                         const int* __restrict__ n2g,
                         float* __restrict__ out) {
    int d  = threadIdx.x;
    int r0 = blockIdx.x * 512;
    if (r0 >= NN) return;
    int r1 = min(r0 + 512, NN);
    float acc = 0.f;
    int gcur = n2g[r0];
    for (int r = r0; r < r1; ++r) {
        int g = n2g[r];
        if (g != gcur) {
            atomicAdd(&out[gcur * DD + d], acc);
            acc = 0.f; gcur = g;
        }
        acc += x[(size_t)r * DD + d];
    }
    atomicAdd(&out[gcur * DD + d], acc);
}

// ---------------- launch -----------------------------------------------------
// Launch order is load-bearing for profiling: ncu captures launch index 5,
// which is k_gemm(layer 0).
extern "C" void kernel_launch(void* const* d_in, const int* in_sizes, int n_in,
                              void* d_out, int out_size) {
    const int*   unit_type   = (const int*)  d_in[0];
    const int*   node_in     = (const int*)  d_in[1];
    const int*   node_out    = (const int*)  d_in[2];
    const int*   relation    = (const int*)  d_in[3];
    const float* edge_weight = (const float*)d_in[4];
    const int*   node2graph  = (const int*)  d_in[5];
    const float* emb         = (const float*)d_in[6];
    const float* W_rel       = (const float*)d_in[7];
    const float* b_rel       = (const float*)d_in[8];
    const float* W_loop      = (const float*)d_in[9];
    const float* b_loop      = (const float*)d_in[10];

    float* out    = (float*)d_out;
    float* out_gf = out;
    float* out_x  = out + GG * DD;

    cudaFuncSetAttribute(k_gemm, cudaFuncAttributeMaxDynamicSharedMemorySize, SMTOT);

    k_setup<<<(NN * DD + 255) / 256, 256>>>(unit_type, emb, W_rel, W_loop,
                                            b_rel, b_loop, out_gf);      // 0
    k_hist<<<(EE + 255) / 256, 256>>>(node_out, relation);               // 1
    k_scan<<<NB1, SCAN_B>>>();                                           // 2
    k_fill<<<(EE + 255) / 256, 256>>>(node_in, node_out, relation,
                                      edge_weight);                      // 3

    for (int L = 0; L < 3; ++L) {
        k_scatter<<<(NRSEG * 32 + 255) / 256, 256>>>(L);                 // 4,6,8
        float* oext = (L == 2) ? out_x : nullptr;
        k_gemm<<<(NN + 127) / 128, 256, SMTOT>>>(L, oext, (L < 2) ? 1 : 0); // 5 <- ncu
    }

    k_segsum<<<(NN + 511) / 512, 128>>>(out_x, node2graph, out_gf);
}